// round 6
// baseline (speedup 1.0000x reference)
#include <cuda_runtime.h>

// Problem constants (from reference setup_inputs)
#define B_TOK   512
#define L_SEQ   50
#define T_TOK   (B_TOK * L_SEQ)   // 25600
#define D_IN    768
#define O_OUT   300
#define N_EXP   8

// Scratch (allocation-free: __device__ globals)
__device__ float g_gates[T_TOK * N_EXP];        // softmax gates  [T, E]
__device__ float g_bw[L_SEQ * N_EXP * O_OUT];   // bias @ W^T     [L, E, O]

// ---------------------------------------------------------------------------
// Kernel 1: gating. One warp per token: z[e] = x[t,:] @ w_gate[:,e], softmax.
// ---------------------------------------------------------------------------
__global__ __launch_bounds__(256) void gates_kernel(
    const float* __restrict__ x, const float* __restrict__ w_gate)
{
    int warp = (blockIdx.x * blockDim.x + threadIdx.x) >> 5;
    int lane = threadIdx.x & 31;
    if (warp >= T_TOK) return;
    const float* xr = x + (size_t)warp * D_IN;

    float z[N_EXP];
#pragma unroll
    for (int e = 0; e < N_EXP; e++) z[e] = 0.f;

    for (int i = lane; i < D_IN; i += 32) {
        float xv = xr[i];
        const float4* wg = reinterpret_cast<const float4*>(w_gate + (size_t)i * N_EXP);
        float4 w0 = wg[0], w1 = wg[1];
        z[0] += xv * w0.x; z[1] += xv * w0.y; z[2] += xv * w0.z; z[3] += xv * w0.w;
        z[4] += xv * w1.x; z[5] += xv * w1.y; z[6] += xv * w1.z; z[7] += xv * w1.w;
    }
#pragma unroll
    for (int e = 0; e < N_EXP; e++) {
#pragma unroll
        for (int off = 16; off; off >>= 1)
            z[e] += __shfl_xor_sync(0xffffffffu, z[e], off);
    }
    // every lane now holds the full 8 logits
    float m = z[0];
#pragma unroll
    for (int e = 1; e < N_EXP; e++) m = fmaxf(m, z[e]);
    float s = 0.f, p[N_EXP];
#pragma unroll
    for (int e = 0; e < N_EXP; e++) { p[e] = expf(z[e] - m); s += p[e]; }
    float inv = 1.f / s;
    if (lane < N_EXP) g_gates[(size_t)warp * N_EXP + lane] = p[lane] * inv;
}

// ---------------------------------------------------------------------------
// Kernel 2: bw[l,e,o] = sum_i expert_bias[e,l,i] * expert_w[e,o,i]
// One block per (l,e); bias row cached in smem.
// ---------------------------------------------------------------------------
__global__ __launch_bounds__(256) void bw_kernel(
    const float* __restrict__ expert_bias, const float* __restrict__ expert_w)
{
    int l = blockIdx.x;   // 0..49
    int e = blockIdx.y;   // 0..7
    __shared__ float sb[D_IN];
    const float* br = expert_bias + ((size_t)e * L_SEQ + l) * D_IN;
    for (int i = threadIdx.x; i < D_IN; i += blockDim.x) sb[i] = br[i];
    __syncthreads();

    for (int o = threadIdx.x; o < O_OUT; o += blockDim.x) {
        const float* wr = expert_w + ((size_t)e * O_OUT + o) * D_IN;
        float s = 0.f;
#pragma unroll 4
        for (int i = 0; i < D_IN; i += 4) {
            float4 w4 = *reinterpret_cast<const float4*>(wr + i);
            s += sb[i] * w4.x + sb[i + 1] * w4.y + sb[i + 2] * w4.z + sb[i + 3] * w4.w;
        }
        g_bw[((size_t)l * N_EXP + e) * O_OUT + o] = s;
    }
}

// ---------------------------------------------------------------------------
// Kernel 3: main fused GEMM.
// Block tile: 64 tokens x 64 outputs, 256 threads (16x16), 4x4 per thread.
// Outer loop over experts; per expert accumulate x@W_e^T, then fold
// out += g[t,e] * (acc - bw[l,e,o]).
// ---------------------------------------------------------------------------
#define TM 64
#define TO 64
#define KT 16
#define APAD 4

__global__ __launch_bounds__(256) void moe_main_kernel(
    const float* __restrict__ x, const float* __restrict__ expert_w,
    float* __restrict__ out)
{
    __shared__ float As[KT][TM + APAD];   // x tile, transposed [k][t]
    __shared__ float Bs[KT][TO + APAD];   // W tile, transposed [k][o]

    const int tb  = blockIdx.x * TM;      // token base
    const int ob  = blockIdx.y * TO;      // output base
    const int tid = threadIdx.x;
    const int tx  = tid & 15;             // output direction (x4)
    const int ty  = tid >> 4;             // token  direction (x4)
    // load mapping: each thread loads one float4 per tile
    const int lrow = tid >> 2;            // 0..63
    const int lc4  = (tid & 3) * 4;       // 0,4,8,12

    float outacc[4][4];
#pragma unroll
    for (int i = 0; i < 4; i++)
#pragma unroll
        for (int j = 0; j < 4; j++) outacc[i][j] = 0.f;

    const int t0 = tb + ty * 4;
    const int o0 = ob + tx * 4;
    const int wo = ob + lrow;             // W row this thread loads
    const bool wvalid = (wo < O_OUT);
    const float* xrow = x + (size_t)(tb + lrow) * D_IN + lc4;

    // per-subtile token -> sequence position (loop-invariant)
    int lpos[4];
#pragma unroll
    for (int i = 0; i < 4; i++) lpos[i] = (t0 + i) % L_SEQ;

    for (int e = 0; e < N_EXP; e++) {
        float acc[4][4];
#pragma unroll
        for (int i = 0; i < 4; i++)
#pragma unroll
            for (int j = 0; j < 4; j++) acc[i][j] = 0.f;

        const float* wrow = expert_w + ((size_t)e * O_OUT + wo) * D_IN + lc4;

        for (int k0 = 0; k0 < D_IN; k0 += KT) {
            float4 xa = *reinterpret_cast<const float4*>(xrow + k0);
            float4 wb = make_float4(0.f, 0.f, 0.f, 0.f);
            if (wvalid) wb = *reinterpret_cast<const float4*>(wrow + k0);

            __syncthreads();   // previous iteration's compute done
            As[lc4 + 0][lrow] = xa.x; As[lc4 + 1][lrow] = xa.y;
            As[lc4 + 2][lrow] = xa.z; As[lc4 + 3][lrow] = xa.w;
            Bs[lc4 + 0][lrow] = wb.x; Bs[lc4 + 1][lrow] = wb.y;
            Bs[lc4 + 2][lrow] = wb.z; Bs[lc4 + 3][lrow] = wb.w;
            __syncthreads();

#pragma unroll
            for (int kk = 0; kk < KT; kk++) {
                float4 a = *reinterpret_cast<const float4*>(&As[kk][ty * 4]);
                float4 b = *reinterpret_cast<const float4*>(&Bs[kk][tx * 4]);
                acc[0][0] += a.x * b.x; acc[0][1] += a.x * b.y;
                acc[0][2] += a.x * b.z; acc[0][3] += a.x * b.w;
                acc[1][0] += a.y * b.x; acc[1][1] += a.y * b.y;
                acc[1][2] += a.y * b.z; acc[1][3] += a.y * b.w;
                acc[2][0] += a.z * b.x; acc[2][1] += a.z * b.y;
                acc[2][2] += a.z * b.z; acc[2][3] += a.z * b.w;
                acc[3][0] += a.w * b.x; acc[3][1] += a.w * b.y;
                acc[3][2] += a.w * b.z; acc[3][3] += a.w * b.w;
            }
        }

        // Fold this expert into the output accumulator
        float gv[4];
#pragma unroll
        for (int i = 0; i < 4; i++)
            gv[i] = g_gates[(size_t)(t0 + i) * N_EXP + e];

#pragma unroll
        for (int i = 0; i < 4; i++) {
            const float* bwr = &g_bw[((size_t)lpos[i] * N_EXP + e) * O_OUT];
#pragma unroll
            for (int j = 0; j < 4; j++) {
                int o = o0 + j;
                float bwv = (o < O_OUT) ? bwr[o] : 0.f;
                outacc[i][j] += gv[i] * (acc[i][j] - bwv);
            }
        }
    }

#pragma unroll
    for (int i = 0; i < 4; i++) {
        int t = t0 + i;
#pragma unroll
        for (int j = 0; j < 4; j++) {
            int o = o0 + j;
            if (o < O_OUT) out[(size_t)t * O_OUT + o] = outacc[i][j];
        }
    }
}

// ---------------------------------------------------------------------------
extern "C" void kernel_launch(void* const* d_in, const int* in_sizes, int n_in,
                              void* d_out, int out_size)
{
    const float* x           = (const float*)d_in[0];  // [B, L, D_IN]
    const float* w_gate      = (const float*)d_in[1];  // [D_IN, E]
    const float* expert_w    = (const float*)d_in[2];  // [E, O, D_IN]
    const float* expert_bias = (const float*)d_in[3];  // [E, L, D_IN]
    float* out = (float*)d_out;                        // [B, L, O]

    (void)in_sizes; (void)n_in; (void)out_size;

    // 1) gates: 25600 warps -> 3200 blocks of 8 warps
    gates_kernel<<<T_TOK / 8, 256>>>(x, w_gate);
    // 2) bw precompute: one block per (l, e)
    bw_kernel<<<dim3(L_SEQ, N_EXP), 256>>>(expert_bias, expert_w);
    // 3) main fused GEMM: 400 token tiles x 5 output tiles
    moe_main_kernel<<<dim3(T_TOK / TM, (O_OUT + TO - 1) / TO), 256>>>(x, expert_w, out);
}

// round 9
// speedup vs baseline: 1.3939x; 1.3939x over previous
#include <cuda_runtime.h>
#include <cuda_bf16.h>
#include <cstdint>

// Problem constants
#define B_TOK   512
#define L_SEQ   50
#define T_TOK   (B_TOK * L_SEQ)   // 25600
#define D_IN    768
#define O_OUT   300
#define O_PAD   320
#define N_EXP   8

// GEMM tiling: out[25600 x 320] = Ag[25600 x 6144] @ Wcat[320 x 6144]^T
#define MT      128                 // tokens per CTA
#define NT      160                 // outputs per CTA  (grid.y = 2)
#define KC      32                  // K elems staged per chunk
#define NCH     (N_EXP * D_IN / KC) // 192 chunks
#define KPE     (D_IN / KC)         // 24 chunks per expert

// SMEM layout (static, 46080 B < 48 KB): padded row stride 40 bf16 = 80 B
#define SSTRIDE 40
#define A_BUF   (MT * SSTRIDE * 2)      // 10240 B
#define B_BUF   (NT * SSTRIDE * 2)      // 12800 B
#define OFF_AHI 0
#define OFF_ALO (A_BUF)                 // 10240
#define OFF_BHI (2 * A_BUF)             // 20480
#define OFF_BLO (2 * A_BUF + B_BUF)     // 33280
#define SM_TOT  (2 * A_BUF + 2 * B_BUF) // 46080

// Scratch (allocation-free: __device__ globals)
__device__ float g_gates[T_TOK * N_EXP];
__device__ float g_bw[L_SEQ * N_EXP * O_OUT];
__device__ float g_gbw[(size_t)T_TOK * O_OUT];
__device__ __align__(16) __nv_bfloat16 g_whi[(size_t)N_EXP * O_PAD * D_IN];
__device__ __align__(16) __nv_bfloat16 g_wlo[(size_t)N_EXP * O_PAD * D_IN];

// ---------------------------------------------------------------------------
// Helpers (baseline ISA only: ldmatrix + mma.sync, sm_80-class features)
// ---------------------------------------------------------------------------
__device__ __forceinline__ uint32_t smem_u32(const void* p) {
    uint32_t a;
    asm("{ .reg .u64 t; cvta.to.shared.u64 t, %1; cvt.u32.u64 %0, t; }"
        : "=r"(a) : "l"(p));
    return a;
}
__device__ __forceinline__ void ldsm_x4(uint32_t* r, uint32_t addr) {
    asm volatile("ldmatrix.sync.aligned.m8n8.x4.shared.b16 {%0,%1,%2,%3}, [%4];"
                 : "=r"(r[0]), "=r"(r[1]), "=r"(r[2]), "=r"(r[3]) : "r"(addr));
}
__device__ __forceinline__ void ldsm_x2(uint32_t* r, uint32_t addr) {
    asm volatile("ldmatrix.sync.aligned.m8n8.x2.shared.b16 {%0,%1}, [%2];"
                 : "=r"(r[0]), "=r"(r[1]) : "r"(addr));
}
__device__ __forceinline__ void mma_bf16(float* d, const uint32_t* a, const uint32_t* b) {
    asm volatile(
        "mma.sync.aligned.m16n8k16.row.col.f32.bf16.bf16.f32 "
        "{%0,%1,%2,%3}, {%4,%5,%6,%7}, {%8,%9}, {%0,%1,%2,%3};"
        : "+f"(d[0]), "+f"(d[1]), "+f"(d[2]), "+f"(d[3])
        : "r"(a[0]), "r"(a[1]), "r"(a[2]), "r"(a[3]), "r"(b[0]), "r"(b[1]));
}
__device__ __forceinline__ void sts64(uint32_t addr, uint32_t v0, uint32_t v1) {
    asm volatile("st.shared.v2.b32 [%0], {%1,%2};" :: "r"(addr), "r"(v0), "r"(v1) : "memory");
}
__device__ __forceinline__ void sts128(uint32_t addr, uint4 v) {
    asm volatile("st.shared.v4.b32 [%0], {%1,%2,%3,%4};"
                 :: "r"(addr), "r"(v.x), "r"(v.y), "r"(v.z), "r"(v.w) : "memory");
}
__device__ __forceinline__ uint32_t pack_bf16x2(__nv_bfloat16 a, __nv_bfloat16 b) {
    __nv_bfloat162 h2(a, b);
    return *reinterpret_cast<uint32_t*>(&h2);
}

// ---------------------------------------------------------------------------
// Kernel 1: gating (unchanged — 46us measured)
// ---------------------------------------------------------------------------
__global__ __launch_bounds__(256) void gates_kernel(
    const float* __restrict__ x, const float* __restrict__ w_gate)
{
    int warp = (blockIdx.x * blockDim.x + threadIdx.x) >> 5;
    int lane = threadIdx.x & 31;
    if (warp >= T_TOK) return;
    const float* xr = x + (size_t)warp * D_IN;

    float z[N_EXP];
#pragma unroll
    for (int e = 0; e < N_EXP; e++) z[e] = 0.f;
    for (int i = lane; i < D_IN; i += 32) {
        float xv = xr[i];
        const float4* wg = reinterpret_cast<const float4*>(w_gate + (size_t)i * N_EXP);
        float4 w0 = wg[0], w1 = wg[1];
        z[0] += xv * w0.x; z[1] += xv * w0.y; z[2] += xv * w0.z; z[3] += xv * w0.w;
        z[4] += xv * w1.x; z[5] += xv * w1.y; z[6] += xv * w1.z; z[7] += xv * w1.w;
    }
#pragma unroll
    for (int e = 0; e < N_EXP; e++) {
#pragma unroll
        for (int off = 16; off; off >>= 1)
            z[e] += __shfl_xor_sync(0xffffffffu, z[e], off);
    }
    float m = z[0];
#pragma unroll
    for (int e = 1; e < N_EXP; e++) m = fmaxf(m, z[e]);
    float s = 0.f, p[N_EXP];
#pragma unroll
    for (int e = 0; e < N_EXP; e++) { p[e] = expf(z[e] - m); s += p[e]; }
    float inv = 1.f / s;
    if (lane < N_EXP) g_gates[(size_t)warp * N_EXP + lane] = p[lane] * inv;
}

// ---------------------------------------------------------------------------
// Kernel 2: bw[l,e,o] = sum_i expert_bias[e,l,i] * expert_w[e,o,i]
// ---------------------------------------------------------------------------
__global__ __launch_bounds__(256) void bw_kernel(
    const float* __restrict__ expert_bias, const float* __restrict__ expert_w)
{
    int l = blockIdx.x, e = blockIdx.y;
    __shared__ float sb[D_IN];
    const float* br = expert_bias + ((size_t)e * L_SEQ + l) * D_IN;
    for (int i = threadIdx.x; i < D_IN; i += blockDim.x) sb[i] = br[i];
    __syncthreads();
    for (int o = threadIdx.x; o < O_OUT; o += blockDim.x) {
        const float* wr = expert_w + ((size_t)e * O_OUT + o) * D_IN;
        float s = 0.f;
#pragma unroll 4
        for (int i = 0; i < D_IN; i += 4) {
            float4 w4 = *reinterpret_cast<const float4*>(wr + i);
            s += sb[i] * w4.x + sb[i + 1] * w4.y + sb[i + 2] * w4.z + sb[i + 3] * w4.w;
        }
        g_bw[((size_t)l * N_EXP + e) * O_OUT + o] = s;
    }
}

// ---------------------------------------------------------------------------
// Kernel 3: gbw[t,o] = sum_e gates[t,e] * bw[l(t),e,o]
// ---------------------------------------------------------------------------
__global__ __launch_bounds__(256) void gbw_kernel()
{
    int l = blockIdx.x;        // 0..49
    int tc = blockIdx.y;       // 0..7
    __shared__ float sbw[N_EXP * O_OUT];
    for (int i = threadIdx.x; i < N_EXP * O_OUT; i += blockDim.x)
        sbw[i] = g_bw[(size_t)l * N_EXP * O_OUT + i];
    __syncthreads();

    for (int bb = 0; bb < 64; bb++) {
        int t = (tc * 64 + bb) * L_SEQ + l;
        float g8[N_EXP];
#pragma unroll
        for (int e = 0; e < N_EXP; e++) g8[e] = g_gates[(size_t)t * N_EXP + e];
        for (int o = threadIdx.x; o < O_OUT; o += blockDim.x) {
            float s = 0.f;
#pragma unroll
            for (int e = 0; e < N_EXP; e++) s += g8[e] * sbw[e * O_OUT + o];
            g_gbw[(size_t)t * O_OUT + o] = s;
        }
    }
}

// ---------------------------------------------------------------------------
// Kernel 4: split expert_w into bf16 hi/lo, padded O 300 -> 320 (zeros)
// ---------------------------------------------------------------------------
__global__ __launch_bounds__(256) void pack_w_kernel(const float* __restrict__ expert_w)
{
    size_t i4 = (size_t)blockIdx.x * blockDim.x + threadIdx.x;
    size_t idx = i4 * 4;
    int e = (int)(idx / ((size_t)O_PAD * D_IN));
    size_t rem = idx % ((size_t)O_PAD * D_IN);
    int o = (int)(rem / D_IN);
    int k = (int)(rem % D_IN);
    float4 v = make_float4(0.f, 0.f, 0.f, 0.f);
    if (o < O_OUT)
        v = *reinterpret_cast<const float4*>(expert_w + ((size_t)e * O_OUT + o) * D_IN + k);
    __nv_bfloat16 h0 = __float2bfloat16_rn(v.x), h1 = __float2bfloat16_rn(v.y);
    __nv_bfloat16 h2 = __float2bfloat16_rn(v.z), h3 = __float2bfloat16_rn(v.w);
    __nv_bfloat16 l0 = __float2bfloat16_rn(v.x - __bfloat162float(h0));
    __nv_bfloat16 l1 = __float2bfloat16_rn(v.y - __bfloat162float(h1));
    __nv_bfloat16 l2 = __float2bfloat16_rn(v.z - __bfloat162float(h2));
    __nv_bfloat16 l3 = __float2bfloat16_rn(v.w - __bfloat162float(h3));
    uint32_t* ph = reinterpret_cast<uint32_t*>(g_whi);
    uint32_t* pl = reinterpret_cast<uint32_t*>(g_wlo);
    ph[i4 * 2]     = pack_bf16x2(h0, h1);
    ph[i4 * 2 + 1] = pack_bf16x2(h2, h3);
    pl[i4 * 2]     = pack_bf16x2(l0, l1);
    pl[i4 * 2 + 1] = pack_bf16x2(l2, l3);
}

// ---------------------------------------------------------------------------
// Kernel 5: main GEMM via mma.sync m16n8k16 bf16 (baseline ISA).
// CTA 128M x 160N, 8 warps (4M x 2N), per-warp 32M x 80N -> 2x10 m16n8 tiles.
// K loop: 192 chunks of 32 (expert e = c/24, k0 = (c%24)*32).
// A chunk built on the fly: a = g[t,e]*x[t,k], split to bf16 hi/lo.
// 3 precision passes per chunk: hi*hi, hi*lo, lo*hi into fp32 accumulators.
// Epilogue: out = acc - gbw.
// ---------------------------------------------------------------------------
__global__ __launch_bounds__(256, 1) void moe_hmma_kernel(
    const float* __restrict__ x, float* __restrict__ out)
{
    __shared__ __align__(16) unsigned char smem_raw[SM_TOT];

    const int tid  = threadIdx.x;
    const int wid  = tid >> 5;
    const int lane = tid & 31;
    const int wm   = wid & 3;          // warp M index (0..3)
    const int wn   = wid >> 2;         // warp N index (0..1)
    const int tb   = blockIdx.x * MT;
    const int ob   = blockIdx.y * NT;

    const uint32_t sb   = smem_u32(smem_raw);
    const uint32_t A_hi = sb + OFF_AHI;
    const uint32_t A_lo = sb + OFF_ALO;
    const uint32_t B_hi = sb + OFF_BHI;
    const uint32_t B_lo = sb + OFF_BLO;

    // ldmatrix lane offsets (bytes)
    const uint32_t laneA = (uint32_t)(((lane & 7) + ((lane >> 3) & 1) * 8) * (SSTRIDE * 2)
                                      + ((lane >> 4) & 1) * 16);
    const int li = lane & 15;
    const uint32_t laneB = (uint32_t)((li & 7) * (SSTRIDE * 2) + (li >> 3) * 16);

    // staging maps
    const int arow = tid >> 1;                 // 0..127
    const int acol = (tid & 1) * 16;           // 0 or 16 (elements)

    float d[2][10][4];
#pragma unroll
    for (int i = 0; i < 2; i++)
#pragma unroll
        for (int j = 0; j < 10; j++)
#pragma unroll
            for (int q = 0; q < 4; q++) d[i][j][q] = 0.f;

    // prefetch registers
    float4 ax[4];
    float  gv;
    uint4  bx[5];

    // ---- prefetch chunk 0 ----
    {
        const int e = 0, k0 = 0;
        gv = g_gates[(size_t)(tb + arow) * N_EXP + e];
#pragma unroll
        for (int j = 0; j < 4; j++)
            ax[j] = *reinterpret_cast<const float4*>(
                x + (size_t)(tb + arow) * D_IN + k0 + acol + j * 4);
#pragma unroll
        for (int t = 0; t < 5; t++) {
            int i = tid + t * 256;             // 0..1279
            int ii = (i >= 640) ? i - 640 : i;
            int brow = ii >> 2, c8 = ii & 3;
            const __nv_bfloat16* src = (i >= 640) ? g_wlo : g_whi;
            bx[t] = *reinterpret_cast<const uint4*>(
                src + ((size_t)(e * O_PAD + ob + brow)) * D_IN + k0 + c8 * 8);
        }
    }

    for (int c = 0; c < NCH; c++) {
        __syncthreads();    // previous chunk's compute done -> smem reusable

        // ---- store staged chunk to SMEM ----
        {
            uint32_t abase = A_hi + (uint32_t)(arow * (SSTRIDE * 2) + acol * 2);
            uint32_t lbase = A_lo + (uint32_t)(arow * (SSTRIDE * 2) + acol * 2);
#pragma unroll
            for (int j = 0; j < 4; j++) {
                float a0 = gv * ax[j].x, a1 = gv * ax[j].y;
                float a2 = gv * ax[j].z, a3 = gv * ax[j].w;
                __nv_bfloat16 h0 = __float2bfloat16_rn(a0), h1 = __float2bfloat16_rn(a1);
                __nv_bfloat16 h2 = __float2bfloat16_rn(a2), h3 = __float2bfloat16_rn(a3);
                __nv_bfloat16 l0 = __float2bfloat16_rn(a0 - __bfloat162float(h0));
                __nv_bfloat16 l1 = __float2bfloat16_rn(a1 - __bfloat162float(h1));
                __nv_bfloat16 l2 = __float2bfloat16_rn(a2 - __bfloat162float(h2));
                __nv_bfloat16 l3 = __float2bfloat16_rn(a3 - __bfloat162float(h3));
                sts64(abase + j * 8, pack_bf16x2(h0, h1), pack_bf16x2(h2, h3));
                sts64(lbase + j * 8, pack_bf16x2(l0, l1), pack_bf16x2(l2, l3));
            }
#pragma unroll
            for (int t = 0; t < 5; t++) {
                int i = tid + t * 256;
                int ii = (i >= 640) ? i - 640 : i;
                int brow = ii >> 2, c8 = ii & 3;
                uint32_t dst = ((i >= 640) ? B_lo : B_hi)
                             + (uint32_t)(brow * (SSTRIDE * 2) + c8 * 16);
                sts128(dst, bx[t]);
            }
        }
        __syncthreads();

        // ---- prefetch next chunk (overlaps compute below) ----
        if (c + 1 < NCH) {
            const int cn = c + 1;
            const int e = cn / KPE, k0 = (cn % KPE) * KC;
            gv = g_gates[(size_t)(tb + arow) * N_EXP + e];
#pragma unroll
            for (int j = 0; j < 4; j++)
                ax[j] = *reinterpret_cast<const float4*>(
                    x + (size_t)(tb + arow) * D_IN + k0 + acol + j * 4);
#pragma unroll
            for (int t = 0; t < 5; t++) {
                int i = tid + t * 256;
                int ii = (i >= 640) ? i - 640 : i;
                int brow = ii >> 2, c8 = ii & 3;
                const __nv_bfloat16* src = (i >= 640) ? g_wlo : g_whi;
                bx[t] = *reinterpret_cast<const uint4*>(
                    src + ((size_t)(e * O_PAD + ob + brow)) * D_IN + k0 + c8 * 8);
            }
        }

        // ---- compute: 3 precision passes, 2 k-steps each ----
#pragma unroll
        for (int p = 0; p < 3; p++) {
            const uint32_t Ab = (p < 2) ? A_hi : A_lo;
            const uint32_t Bb = (p == 1) ? B_lo : B_hi;
#pragma unroll
            for (int ks = 0; ks < 2; ks++) {
                uint32_t af[2][4];
#pragma unroll
                for (int mi = 0; mi < 2; mi++)
                    ldsm_x4(af[mi], Ab + laneA
                            + (uint32_t)((wm * 32 + mi * 16) * (SSTRIDE * 2) + ks * 32));
#pragma unroll
                for (int nt = 0; nt < 10; nt++) {
                    uint32_t bf[2];
                    ldsm_x2(bf, Bb + laneB
                            + (uint32_t)((wn * 80 + nt * 8) * (SSTRIDE * 2) + ks * 32));
                    mma_bf16(d[0][nt], af[0], bf);
                    mma_bf16(d[1][nt], af[1], bf);
                }
            }
        }
    }

    // ---- epilogue: out = acc - gbw ----
    const int grp = lane >> 2;
    const int t4  = lane & 3;
#pragma unroll
    for (int mi = 0; mi < 2; mi++) {
        const int t0 = tb + wm * 32 + mi * 16 + grp;
#pragma unroll
        for (int nt = 0; nt < 10; nt++) {
            const int o = ob + wn * 80 + nt * 8 + t4 * 2;
            if (o < O_OUT) {
                {
                    const float2 gb = *reinterpret_cast<const float2*>(
                        g_gbw + (size_t)t0 * O_OUT + o);
                    float2 w = make_float2(d[mi][nt][0] - gb.x, d[mi][nt][1] - gb.y);
                    *reinterpret_cast<float2*>(out + (size_t)t0 * O_OUT + o) = w;
                }
                {
                    const int t1 = t0 + 8;
                    const float2 gb = *reinterpret_cast<const float2*>(
                        g_gbw + (size_t)t1 * O_OUT + o);
                    float2 w = make_float2(d[mi][nt][2] - gb.x, d[mi][nt][3] - gb.y);
                    *reinterpret_cast<float2*>(out + (size_t)t1 * O_OUT + o) = w;
                }
            }
        }
    }
}

// ---------------------------------------------------------------------------
extern "C" void kernel_launch(void* const* d_in, const int* in_sizes, int n_in,
                              void* d_out, int out_size)
{
    const float* x           = (const float*)d_in[0];  // [B, L, D_IN]
    const float* w_gate      = (const float*)d_in[1];  // [D_IN, E]
    const float* expert_w    = (const float*)d_in[2];  // [E, O, D_IN]
    const float* expert_bias = (const float*)d_in[3];  // [E, L, D_IN]
    float* out = (float*)d_out;                        // [B, L, O]
    (void)in_sizes; (void)n_in; (void)out_size;

    gates_kernel<<<T_TOK / 8, 256>>>(x, w_gate);
    bw_kernel<<<dim3(L_SEQ, N_EXP), 256>>>(expert_bias, expert_w);
    gbw_kernel<<<dim3(L_SEQ, N_EXP), 256>>>();
    pack_w_kernel<<<(N_EXP * O_PAD * D_IN / 4) / 256, 256>>>(expert_w);
    moe_hmma_kernel<<<dim3(T_TOK / MT, O_PAD / NT), 256>>>(x, out);
}

// round 10
// speedup vs baseline: 2.4043x; 1.7249x over previous
#include <cuda_runtime.h>
#include <cuda_bf16.h>
#include <cstdint>

// Problem constants
#define B_TOK   512
#define L_SEQ   50
#define T_TOK   (B_TOK * L_SEQ)   // 25600
#define D_IN    768
#define O_OUT   300
#define O_PAD   320
#define N_EXP   8

// Main GEMM tiling
#define MT      128                 // tokens per CTA (grid.x = 200)
#define NT      160                 // outputs per CTA (grid.y = 2)
#define KC      32                  // K elems per chunk
#define NCHUNK  (D_IN / KC)         // 24

// SMEM (dynamic): stride 40 bf16 = 80 B rows (conflict-free for ldmatrix)
#define RS      80                  // row stride bytes
#define A_BYTES (MT * RS)           // 10240 per (hi|lo)
#define B_BYTES (NT * RS)           // 12800 per expert per (hi|lo)
#define OFF_ALO A_BYTES
#define OFF_B   (2 * A_BYTES)       // 20480; expert e: +e*2*B_BYTES, lo at +B_BYTES
#define SMEM_MAIN (OFF_B + N_EXP * 2 * B_BYTES)   // 225280

// Scratch
__device__ float g_gates[T_TOK * N_EXP];
__device__ float g_gbw[(size_t)T_TOK * O_OUT];
__device__ __align__(16) __nv_bfloat16 g_xhi[(size_t)T_TOK * D_IN];
__device__ __align__(16) __nv_bfloat16 g_xlo[(size_t)T_TOK * D_IN];
__device__ __align__(16) __nv_bfloat16 g_whi[(size_t)N_EXP * O_PAD * D_IN];
__device__ __align__(16) __nv_bfloat16 g_wlo[(size_t)N_EXP * O_PAD * D_IN];

// ---------------------------------------------------------------------------
// Helpers (baseline ISA: ldmatrix + mma.sync only — sm_103 has no 'a' features)
// ---------------------------------------------------------------------------
__device__ __forceinline__ uint32_t smem_u32(const void* p) {
    uint32_t a;
    asm("{ .reg .u64 t; cvta.to.shared.u64 t, %1; cvt.u32.u64 %0, t; }"
        : "=r"(a) : "l"(p));
    return a;
}
__device__ __forceinline__ void ldsm_x4(uint32_t* r, uint32_t addr) {
    asm volatile("ldmatrix.sync.aligned.m8n8.x4.shared.b16 {%0,%1,%2,%3}, [%4];"
                 : "=r"(r[0]), "=r"(r[1]), "=r"(r[2]), "=r"(r[3]) : "r"(addr));
}
__device__ __forceinline__ void ldsm_x2(uint32_t* r, uint32_t addr) {
    asm volatile("ldmatrix.sync.aligned.m8n8.x2.shared.b16 {%0,%1}, [%2];"
                 : "=r"(r[0]), "=r"(r[1]) : "r"(addr));
}
__device__ __forceinline__ void mma_bf16(float* d, const uint32_t* a, const uint32_t* b) {
    asm volatile(
        "mma.sync.aligned.m16n8k16.row.col.f32.bf16.bf16.f32 "
        "{%0,%1,%2,%3}, {%4,%5,%6,%7}, {%8,%9}, {%0,%1,%2,%3};"
        : "+f"(d[0]), "+f"(d[1]), "+f"(d[2]), "+f"(d[3])
        : "r"(a[0]), "r"(a[1]), "r"(a[2]), "r"(a[3]), "r"(b[0]), "r"(b[1]));
}
__device__ __forceinline__ void sts128(uint32_t addr, uint4 v) {
    asm volatile("st.shared.v4.b32 [%0], {%1,%2,%3,%4};"
                 :: "r"(addr), "r"(v.x), "r"(v.y), "r"(v.z), "r"(v.w) : "memory");
}
__device__ __forceinline__ uint32_t pack_bf16x2(__nv_bfloat16 a, __nv_bfloat16 b) {
    __nv_bfloat162 h2(a, b);
    return *reinterpret_cast<uint32_t*>(&h2);
}

// ---------------------------------------------------------------------------
// Kernel 1: fused prologue — gates | pack_x | pack_w by blockIdx range.
// ---------------------------------------------------------------------------
#define NG   3200    // gates blocks (8 warps each -> 25600 tokens)
#define NPX  19200   // pack_x blocks (256 float4 each)
#define NPW  1920    // pack_w blocks

__global__ __launch_bounds__(256) void prologue_kernel(
    const float* __restrict__ x, const float* __restrict__ w_gate,
    const float* __restrict__ expert_w)
{
    const int b = blockIdx.x;
    const int tid = threadIdx.x;

    if (b < NG) {
        // ---- gating: one warp per token ----
        int warp = b * 8 + (tid >> 5);
        int lane = tid & 31;
        const float* xr = x + (size_t)warp * D_IN;
        float z[N_EXP];
#pragma unroll
        for (int e = 0; e < N_EXP; e++) z[e] = 0.f;
        for (int i = lane; i < D_IN; i += 32) {
            float xv = xr[i];
            const float4* wg = reinterpret_cast<const float4*>(w_gate + (size_t)i * N_EXP);
            float4 w0 = wg[0], w1 = wg[1];
            z[0] += xv * w0.x; z[1] += xv * w0.y; z[2] += xv * w0.z; z[3] += xv * w0.w;
            z[4] += xv * w1.x; z[5] += xv * w1.y; z[6] += xv * w1.z; z[7] += xv * w1.w;
        }
#pragma unroll
        for (int e = 0; e < N_EXP; e++) {
#pragma unroll
            for (int off = 16; off; off >>= 1)
                z[e] += __shfl_xor_sync(0xffffffffu, z[e], off);
        }
        float m = z[0];
#pragma unroll
        for (int e = 1; e < N_EXP; e++) m = fmaxf(m, z[e]);
        float s = 0.f, p[N_EXP];
#pragma unroll
        for (int e = 0; e < N_EXP; e++) { p[e] = expf(z[e] - m); s += p[e]; }
        float inv = 1.f / s;
        if (lane < N_EXP) g_gates[(size_t)warp * N_EXP + lane] = p[lane] * inv;
    } else if (b < NG + NPX) {
        // ---- pack x -> bf16 hi/lo ----
        size_t i4 = (size_t)(b - NG) * 256 + tid;
        float4 v = reinterpret_cast<const float4*>(x)[i4];
        __nv_bfloat16 h0 = __float2bfloat16_rn(v.x), h1 = __float2bfloat16_rn(v.y);
        __nv_bfloat16 h2 = __float2bfloat16_rn(v.z), h3 = __float2bfloat16_rn(v.w);
        __nv_bfloat16 l0 = __float2bfloat16_rn(v.x - __bfloat162float(h0));
        __nv_bfloat16 l1 = __float2bfloat16_rn(v.y - __bfloat162float(h1));
        __nv_bfloat16 l2 = __float2bfloat16_rn(v.z - __bfloat162float(h2));
        __nv_bfloat16 l3 = __float2bfloat16_rn(v.w - __bfloat162float(h3));
        uint2 hh = make_uint2(pack_bf16x2(h0, h1), pack_bf16x2(h2, h3));
        uint2 ll = make_uint2(pack_bf16x2(l0, l1), pack_bf16x2(l2, l3));
        reinterpret_cast<uint2*>(g_xhi)[i4] = hh;
        reinterpret_cast<uint2*>(g_xlo)[i4] = ll;
    } else {
        // ---- pack expert_w -> bf16 hi/lo, O padded 300 -> 320 ----
        size_t i4 = (size_t)(b - NG - NPX) * 256 + tid;
        size_t idx = i4 * 4;
        int e = (int)(idx / ((size_t)O_PAD * D_IN));
        size_t rem = idx % ((size_t)O_PAD * D_IN);
        int o = (int)(rem / D_IN);
        int k = (int)(rem % D_IN);
        float4 v = make_float4(0.f, 0.f, 0.f, 0.f);
        if (o < O_OUT)
            v = *reinterpret_cast<const float4*>(
                expert_w + ((size_t)e * O_OUT + o) * D_IN + k);
        __nv_bfloat16 h0 = __float2bfloat16_rn(v.x), h1 = __float2bfloat16_rn(v.y);
        __nv_bfloat16 h2 = __float2bfloat16_rn(v.z), h3 = __float2bfloat16_rn(v.w);
        __nv_bfloat16 l0 = __float2bfloat16_rn(v.x - __bfloat162float(h0));
        __nv_bfloat16 l1 = __float2bfloat16_rn(v.y - __bfloat162float(h1));
        __nv_bfloat16 l2 = __float2bfloat16_rn(v.z - __bfloat162float(h2));
        __nv_bfloat16 l3 = __float2bfloat16_rn(v.w - __bfloat162float(h3));
        uint2 hh = make_uint2(pack_bf16x2(h0, h1), pack_bf16x2(h2, h3));
        uint2 ll = make_uint2(pack_bf16x2(l0, l1), pack_bf16x2(l2, l3));
        reinterpret_cast<uint2*>(g_whi)[i4] = hh;
        reinterpret_cast<uint2*>(g_wlo)[i4] = ll;
    }
}

// ---------------------------------------------------------------------------
// Kernel 2: fused bw + gbw.  Block (l, o-range of 75):
//   sbw[e][oo] = bias[e,l,:] . W[e,o,:]   then
//   g_gbw[t, o] = sum_e gates[t,e] * sbw[e][oo]  for all 512 b at this l.
// ---------------------------------------------------------------------------
#define OCH 75
__global__ __launch_bounds__(256) void bw_gbw_kernel(
    const float* __restrict__ expert_bias, const float* __restrict__ expert_w)
{
    const int l = blockIdx.x;
    const int ob4 = blockIdx.y * OCH;
    const int tid = threadIdx.x;

    __shared__ float sbias[N_EXP][D_IN];      // 24576 B
    __shared__ float sbw[N_EXP][OCH + 1];     // padded

    for (int i = tid; i < N_EXP * D_IN / 4; i += 256) {
        int e = i / (D_IN / 4), kk = i % (D_IN / 4);
        float4 v = *reinterpret_cast<const float4*>(
            expert_bias + ((size_t)e * L_SEQ + l) * D_IN + kk * 4);
        *reinterpret_cast<float4*>(&sbias[e][kk * 4]) = v;
    }
    __syncthreads();

    for (int i = tid; i < N_EXP * OCH; i += 256) {
        int e = i / OCH, oo = i % OCH;
        const float* wr = expert_w + ((size_t)e * O_OUT + ob4 + oo) * D_IN;
        float s = 0.f;
#pragma unroll 4
        for (int k = 0; k < D_IN; k += 4) {
            float4 w4 = *reinterpret_cast<const float4*>(wr + k);
            s += sbias[e][k] * w4.x + sbias[e][k + 1] * w4.y
               + sbias[e][k + 2] * w4.z + sbias[e][k + 3] * w4.w;
        }
        sbw[e][oo] = s;
    }
    __syncthreads();

    for (int i = tid; i < B_TOK * OCH; i += 256) {
        int bb = i / OCH, oo = i % OCH;
        int t = bb * L_SEQ + l;
        const float4* gp = reinterpret_cast<const float4*>(g_gates + (size_t)t * N_EXP);
        float4 ga = gp[0], gb = gp[1];
        float s = ga.x * sbw[0][oo] + ga.y * sbw[1][oo]
                + ga.z * sbw[2][oo] + ga.w * sbw[3][oo]
                + gb.x * sbw[4][oo] + gb.y * sbw[5][oo]
                + gb.z * sbw[6][oo] + gb.w * sbw[7][oo];
        g_gbw[(size_t)t * O_OUT + ob4 + oo] = s;
    }
}

// ---------------------------------------------------------------------------
// Kernel 3: main GEMM. 512 threads = 16 warps (4M x 4N); warp tile 32M x 40N.
// Per chunk: stage A(hi/lo) + B(8 experts, hi/lo) [pure uint4 copies], then
// per expert: fresh dd accumulates 3 precision passes; fold outacc += g_e*dd.
// Epilogue: out = outacc - gbw.
// ---------------------------------------------------------------------------
extern __shared__ unsigned char dsmem[];

__global__ __launch_bounds__(512, 1) void moe_hmma_kernel(float* __restrict__ out)
{
    const int tid  = threadIdx.x;
    const int wid  = tid >> 5;
    const int lane = tid & 31;
    const int wm   = wid & 3;           // M group (32 rows)
    const int wn   = wid >> 2;          // N group (40 cols)
    const int tb   = blockIdx.x * MT;
    const int ob   = blockIdx.y * NT;

    const uint32_t sb   = smem_u32(dsmem);
    const uint32_t A_hi = sb;
    const uint32_t A_lo = sb + OFF_ALO;
    const uint32_t Bbas = sb + OFF_B;

    // ldmatrix lane offsets (stride RS=80 B, conflict-free)
    const uint32_t laneA  = (uint32_t)(((lane & 7) + ((lane >> 3) & 1) * 8) * RS
                                       + ((lane >> 4) & 1) * 16);
    const uint32_t laneB4 = (uint32_t)(((lane & 7) + ((lane >> 4) & 1) * 8) * RS
                                       + ((lane >> 3) & 1) * 16);
    const int li = lane & 15;
    const uint32_t laneB2 = (uint32_t)((li & 7) * RS + (li >> 3) * 16);

    const int grp = lane >> 2;
    const int trow0 = tb + wm * 32 + grp;        // mi = 0
    const int trow1 = trow0 + 16;                // mi = 1

    float outacc[2][5][4];
#pragma unroll
    for (int i = 0; i < 2; i++)
#pragma unroll
        for (int j = 0; j < 5; j++)
#pragma unroll
            for (int q = 0; q < 4; q++) outacc[i][j][q] = 0.f;

    for (int c = 0; c < NCHUNK; c++) {
        const int c0 = c * KC;
        __syncthreads();   // previous chunk's compute done

        // ---- stage A: 2x512 uint4 ----
        {
            int row = tid >> 2, c8 = tid & 3;
            size_t gi = (size_t)(tb + row) * D_IN + c0 + c8 * 8;
            uint32_t dof = (uint32_t)(row * RS + c8 * 16);
            sts128(A_hi + dof, *reinterpret_cast<const uint4*>(g_xhi + gi));
            sts128(A_lo + dof, *reinterpret_cast<const uint4*>(g_xlo + gi));
        }
        // ---- stage B: 20x512 uint4 (8 experts x hi/lo x 160x32) ----
#pragma unroll
        for (int t = 0; t < 20; t++) {
            int i = tid + t * 512;
            int e = i / 1280;
            int rem = i - e * 1280;
            int lohalf = rem >= 640;
            int rr = lohalf ? rem - 640 : rem;
            int r = rr >> 2, c8 = rr & 3;
            const __nv_bfloat16* src = lohalf ? g_wlo : g_whi;
            uint4 v = *reinterpret_cast<const uint4*>(
                src + ((size_t)e * O_PAD + ob + r) * D_IN + c0 + c8 * 8);
            sts128(Bbas + (uint32_t)(e * (2 * B_BYTES) + lohalf * B_BYTES
                                     + r * RS + c8 * 16), v);
        }
        __syncthreads();

#pragma unroll 1
        for (int e = 0; e < N_EXP; e++) {
            const uint32_t Bh = Bbas + (uint32_t)(e * (2 * B_BYTES));
            const uint32_t Bl = Bh + B_BYTES;

            float dd[2][5][4];
#pragma unroll
            for (int i = 0; i < 2; i++)
#pragma unroll
                for (int j = 0; j < 5; j++)
#pragma unroll
                    for (int q = 0; q < 4; q++) dd[i][j][q] = 0.f;

#pragma unroll
            for (int p = 0; p < 3; p++) {
                const uint32_t Ab = (p < 2) ? A_hi : A_lo;
                const uint32_t Bb = (p == 1) ? Bl : Bh;
#pragma unroll
                for (int ks = 0; ks < 2; ks++) {
                    uint32_t af[2][4];
#pragma unroll
                    for (int mi = 0; mi < 2; mi++)
                        ldsm_x4(af[mi], Ab + laneA
                                + (uint32_t)((wm * 32 + mi * 16) * RS + ks * 32));
#pragma unroll
                    for (int np = 0; np < 2; np++) {
                        uint32_t b4[4];
                        ldsm_x4(b4, Bb + laneB4
                                + (uint32_t)((wn * 40 + np * 16) * RS + ks * 32));
                        mma_bf16(dd[0][np * 2],     af[0], b4);
                        mma_bf16(dd[1][np * 2],     af[1], b4);
                        mma_bf16(dd[0][np * 2 + 1], af[0], b4 + 2);
                        mma_bf16(dd[1][np * 2 + 1], af[1], b4 + 2);
                    }
                    uint32_t b2[2];
                    ldsm_x2(b2, Bb + laneB2 + (uint32_t)((wn * 40 + 32) * RS + ks * 32));
                    mma_bf16(dd[0][4], af[0], b2);
                    mma_bf16(dd[1][4], af[1], b2);
                }
            }

            // ---- fold: outacc += g * dd ----
            float g00 = g_gates[(size_t)trow0 * N_EXP + e];
            float g01 = g_gates[(size_t)(trow0 + 8) * N_EXP + e];
            float g10 = g_gates[(size_t)trow1 * N_EXP + e];
            float g11 = g_gates[(size_t)(trow1 + 8) * N_EXP + e];
#pragma unroll
            for (int nt = 0; nt < 5; nt++) {
                outacc[0][nt][0] += g00 * dd[0][nt][0];
                outacc[0][nt][1] += g00 * dd[0][nt][1];
                outacc[0][nt][2] += g01 * dd[0][nt][2];
                outacc[0][nt][3] += g01 * dd[0][nt][3];
                outacc[1][nt][0] += g10 * dd[1][nt][0];
                outacc[1][nt][1] += g10 * dd[1][nt][1];
                outacc[1][nt][2] += g11 * dd[1][nt][2];
                outacc[1][nt][3] += g11 * dd[1][nt][3];
            }
        }
    }

    // ---- epilogue: out = outacc - gbw ----
#pragma unroll
    for (int mi = 0; mi < 2; mi++) {
        const int t0 = (mi == 0) ? trow0 : trow1;
#pragma unroll
        for (int nt = 0; nt < 5; nt++) {
            const int o = ob + wn * 40 + nt * 8 + (lane & 3) * 2;
            if (o < O_OUT) {
                {
                    const float2 gb = *reinterpret_cast<const float2*>(
                        g_gbw + (size_t)t0 * O_OUT + o);
                    float2 w = make_float2(outacc[mi][nt][0] - gb.x,
                                           outacc[mi][nt][1] - gb.y);
                    *reinterpret_cast<float2*>(out + (size_t)t0 * O_OUT + o) = w;
                }
                {
                    const int t1 = t0 + 8;
                    const float2 gb = *reinterpret_cast<const float2*>(
                        g_gbw + (size_t)t1 * O_OUT + o);
                    float2 w = make_float2(outacc[mi][nt][2] - gb.x,
                                           outacc[mi][nt][3] - gb.y);
                    *reinterpret_cast<float2*>(out + (size_t)t1 * O_OUT + o) = w;
                }
            }
        }
    }
}

// ---------------------------------------------------------------------------
extern "C" void kernel_launch(void* const* d_in, const int* in_sizes, int n_in,
                              void* d_out, int out_size)
{
    const float* x           = (const float*)d_in[0];
    const float* w_gate      = (const float*)d_in[1];
    const float* expert_w    = (const float*)d_in[2];
    const float* expert_bias = (const float*)d_in[3];
    float* out = (float*)d_out;
    (void)in_sizes; (void)n_in; (void)out_size;

    cudaFuncSetAttribute(moe_hmma_kernel,
                         cudaFuncAttributeMaxDynamicSharedMemorySize, SMEM_MAIN);

    prologue_kernel<<<NG + NPX + NPW, 256>>>(x, w_gate, expert_w);
    bw_gbw_kernel<<<dim3(L_SEQ, O_OUT / OCH), 256>>>(expert_bias, expert_w);
    moe_hmma_kernel<<<dim3(T_TOK / MT, O_PAD / NT), 512, SMEM_MAIN>>>(out);
}

// round 12
// speedup vs baseline: 2.6510x; 1.1026x over previous
#include <cuda_runtime.h>
#include <cuda_bf16.h>
#include <cstdint>

// Problem constants
#define B_TOK   512
#define L_SEQ   50
#define T_TOK   (B_TOK * L_SEQ)   // 25600
#define D_IN    768
#define O_OUT   300
#define O_PAD   320
#define N_EXP   8

// Main GEMM tiling
#define MT      128                 // tokens per CTA (grid.x = 200)
#define NT      160                 // outputs per CTA (grid.y = 2)
#define KC      32                  // K elems per chunk
#define NCHUNK  (D_IN / KC)         // 24

// SMEM: stride 40 bf16 = 80 B rows (conflict-free ldmatrix)
#define RS      80
#define A_BYTES (MT * RS)           // 10240 per (hi|lo)
#define B_BYTES (NT * RS)           // 12800 per expert per (hi|lo)
#define OFF_ALO A_BYTES
#define OFF_B   (2 * A_BYTES)       // expert e: +e*2*B_BYTES, lo at +B_BYTES
#define OFF_G   (OFF_B + N_EXP * 2 * B_BYTES)     // 225280
#define SMEM_MAIN (OFF_G + MT * N_EXP * 4)        // 229376

// Scratch
__device__ float g_gates[T_TOK * N_EXP];
__device__ float g_gbw[(size_t)T_TOK * O_OUT];
__device__ __align__(16) __nv_bfloat16 g_xhi[(size_t)T_TOK * D_IN];
__device__ __align__(16) __nv_bfloat16 g_xlo[(size_t)T_TOK * D_IN];
__device__ __align__(16) __nv_bfloat16 g_whi[(size_t)N_EXP * O_PAD * D_IN];
__device__ __align__(16) __nv_bfloat16 g_wlo[(size_t)N_EXP * O_PAD * D_IN];

// ---------------------------------------------------------------------------
// Helpers (baseline ISA only — sm_103 has no 'a' features)
// ---------------------------------------------------------------------------
__device__ __forceinline__ uint32_t smem_u32(const void* p) {
    uint32_t a;
    asm("{ .reg .u64 t; cvta.to.shared.u64 t, %1; cvt.u32.u64 %0, t; }"
        : "=r"(a) : "l"(p));
    return a;
}
__device__ __forceinline__ void ldsm_x4(uint32_t* r, uint32_t addr) {
    asm volatile("ldmatrix.sync.aligned.m8n8.x4.shared.b16 {%0,%1,%2,%3}, [%4];"
                 : "=r"(r[0]), "=r"(r[1]), "=r"(r[2]), "=r"(r[3]) : "r"(addr));
}
__device__ __forceinline__ void ldsm_x2(uint32_t* r, uint32_t addr) {
    asm volatile("ldmatrix.sync.aligned.m8n8.x2.shared.b16 {%0,%1}, [%2];"
                 : "=r"(r[0]), "=r"(r[1]) : "r"(addr));
}
__device__ __forceinline__ void mma_bf16(float* d, const uint32_t* a, const uint32_t* b) {
    asm volatile(
        "mma.sync.aligned.m16n8k16.row.col.f32.bf16.bf16.f32 "
        "{%0,%1,%2,%3}, {%4,%5,%6,%7}, {%8,%9}, {%0,%1,%2,%3};"
        : "+f"(d[0]), "+f"(d[1]), "+f"(d[2]), "+f"(d[3])
        : "r"(a[0]), "r"(a[1]), "r"(a[2]), "r"(a[3]), "r"(b[0]), "r"(b[1]));
}
__device__ __forceinline__ void cp_async16(uint32_t dst, const void* src) {
    asm volatile("cp.async.cg.shared.global [%0], [%1], 16;"
                 :: "r"(dst), "l"(src) : "memory");
}
__device__ __forceinline__ void cp_commit_wait0() {
    asm volatile("cp.async.commit_group;" ::: "memory");
    asm volatile("cp.async.wait_group 0;" ::: "memory");
}
__device__ __forceinline__ uint32_t pack_bf16x2(__nv_bfloat16 a, __nv_bfloat16 b) {
    __nv_bfloat162 h2(a, b);
    return *reinterpret_cast<uint32_t*>(&h2);
}

// ---------------------------------------------------------------------------
// Kernel 1: fused prologue — gates | pack_x | pack_w by blockIdx range.
// ---------------------------------------------------------------------------
#define NG   3200
#define NPX  19200
#define NPW  1920

__global__ __launch_bounds__(256) void prologue_kernel(
    const float* __restrict__ x, const float* __restrict__ w_gate,
    const float* __restrict__ expert_w)
{
    const int b = blockIdx.x;
    const int tid = threadIdx.x;

    if (b < NG) {
        int warp = b * 8 + (tid >> 5);
        int lane = tid & 31;
        const float* xr = x + (size_t)warp * D_IN;
        float z[N_EXP];
#pragma unroll
        for (int e = 0; e < N_EXP; e++) z[e] = 0.f;
        for (int i = lane; i < D_IN; i += 32) {
            float xv = xr[i];
            const float4* wg = reinterpret_cast<const float4*>(w_gate + (size_t)i * N_EXP);
            float4 w0 = wg[0], w1 = wg[1];
            z[0] += xv * w0.x; z[1] += xv * w0.y; z[2] += xv * w0.z; z[3] += xv * w0.w;
            z[4] += xv * w1.x; z[5] += xv * w1.y; z[6] += xv * w1.z; z[7] += xv * w1.w;
        }
#pragma unroll
        for (int e = 0; e < N_EXP; e++) {
#pragma unroll
            for (int off = 16; off; off >>= 1)
                z[e] += __shfl_xor_sync(0xffffffffu, z[e], off);
        }
        float m = z[0];
#pragma unroll
        for (int e = 1; e < N_EXP; e++) m = fmaxf(m, z[e]);
        float s = 0.f, p[N_EXP];
#pragma unroll
        for (int e = 0; e < N_EXP; e++) { p[e] = expf(z[e] - m); s += p[e]; }
        float inv = 1.f / s;
        if (lane < N_EXP) g_gates[(size_t)warp * N_EXP + lane] = p[lane] * inv;
    } else if (b < NG + NPX) {
        size_t i4 = (size_t)(b - NG) * 256 + tid;
        float4 v = reinterpret_cast<const float4*>(x)[i4];
        __nv_bfloat16 h0 = __float2bfloat16_rn(v.x), h1 = __float2bfloat16_rn(v.y);
        __nv_bfloat16 h2 = __float2bfloat16_rn(v.z), h3 = __float2bfloat16_rn(v.w);
        __nv_bfloat16 l0 = __float2bfloat16_rn(v.x - __bfloat162float(h0));
        __nv_bfloat16 l1 = __float2bfloat16_rn(v.y - __bfloat162float(h1));
        __nv_bfloat16 l2 = __float2bfloat16_rn(v.z - __bfloat162float(h2));
        __nv_bfloat16 l3 = __float2bfloat16_rn(v.w - __bfloat162float(h3));
        reinterpret_cast<uint2*>(g_xhi)[i4] = make_uint2(pack_bf16x2(h0, h1), pack_bf16x2(h2, h3));
        reinterpret_cast<uint2*>(g_xlo)[i4] = make_uint2(pack_bf16x2(l0, l1), pack_bf16x2(l2, l3));
    } else {
        size_t i4 = (size_t)(b - NG - NPX) * 256 + tid;
        size_t idx = i4 * 4;
        int e = (int)(idx / ((size_t)O_PAD * D_IN));
        size_t rem = idx % ((size_t)O_PAD * D_IN);
        int o = (int)(rem / D_IN);
        int k = (int)(rem % D_IN);
        float4 v = make_float4(0.f, 0.f, 0.f, 0.f);
        if (o < O_OUT)
            v = *reinterpret_cast<const float4*>(
                expert_w + ((size_t)e * O_OUT + o) * D_IN + k);
        __nv_bfloat16 h0 = __float2bfloat16_rn(v.x), h1 = __float2bfloat16_rn(v.y);
        __nv_bfloat16 h2 = __float2bfloat16_rn(v.z), h3 = __float2bfloat16_rn(v.w);
        __nv_bfloat16 l0 = __float2bfloat16_rn(v.x - __bfloat162float(h0));
        __nv_bfloat16 l1 = __float2bfloat16_rn(v.y - __bfloat162float(h1));
        __nv_bfloat16 l2 = __float2bfloat16_rn(v.z - __bfloat162float(h2));
        __nv_bfloat16 l3 = __float2bfloat16_rn(v.w - __bfloat162float(h3));
        reinterpret_cast<uint2*>(g_whi)[i4] = make_uint2(pack_bf16x2(h0, h1), pack_bf16x2(h2, h3));
        reinterpret_cast<uint2*>(g_wlo)[i4] = make_uint2(pack_bf16x2(l0, l1), pack_bf16x2(l2, l3));
    }
}

// ---------------------------------------------------------------------------
// Kernel 2: fused bw + gbw (unchanged)
// ---------------------------------------------------------------------------
#define OCH 75
__global__ __launch_bounds__(256) void bw_gbw_kernel(
    const float* __restrict__ expert_bias, const float* __restrict__ expert_w)
{
    const int l = blockIdx.x;
    const int ob4 = blockIdx.y * OCH;
    const int tid = threadIdx.x;

    __shared__ float sbias[N_EXP][D_IN];
    __shared__ float sbw[N_EXP][OCH + 1];

    for (int i = tid; i < N_EXP * D_IN / 4; i += 256) {
        int e = i / (D_IN / 4), kk = i % (D_IN / 4);
        float4 v = *reinterpret_cast<const float4*>(
            expert_bias + ((size_t)e * L_SEQ + l) * D_IN + kk * 4);
        *reinterpret_cast<float4*>(&sbias[e][kk * 4]) = v;
    }
    __syncthreads();

    for (int i = tid; i < N_EXP * OCH; i += 256) {
        int e = i / OCH, oo = i % OCH;
        const float* wr = expert_w + ((size_t)e * O_OUT + ob4 + oo) * D_IN;
        float s = 0.f;
#pragma unroll 4
        for (int k = 0; k < D_IN; k += 4) {
            float4 w4 = *reinterpret_cast<const float4*>(wr + k);
            s += sbias[e][k] * w4.x + sbias[e][k + 1] * w4.y
               + sbias[e][k + 2] * w4.z + sbias[e][k + 3] * w4.w;
        }
        sbw[e][oo] = s;
    }
    __syncthreads();

    for (int i = tid; i < B_TOK * OCH; i += 256) {
        int bb = i / OCH, oo = i % OCH;
        int t = bb * L_SEQ + l;
        const float4* gp = reinterpret_cast<const float4*>(g_gates + (size_t)t * N_EXP);
        float4 ga = gp[0], gb = gp[1];
        float s = ga.x * sbw[0][oo] + ga.y * sbw[1][oo]
                + ga.z * sbw[2][oo] + ga.w * sbw[3][oo]
                + gb.x * sbw[4][oo] + gb.y * sbw[5][oo]
                + gb.z * sbw[6][oo] + gb.w * sbw[7][oo];
        g_gbw[(size_t)t * O_OUT + ob4 + oo] = s;
    }
}

// ---------------------------------------------------------------------------
// Kernel 3: main GEMM. 512 threads, 16 warps (4M x 4N), warp tile 32M x 40N.
// ks-outer: A fragments register-resident across all experts & passes.
// B_hi reused for passes 0&2; B_lo overwrites same regs for pass 1.
// Gate fold per (expert, kstep) — exact by linearity.
// ---------------------------------------------------------------------------
extern __shared__ unsigned char dsmem[];

__global__ __launch_bounds__(512, 1) void moe_hmma_kernel(float* __restrict__ out)
{
    const int tid  = threadIdx.x;
    const int lane = tid & 31;
    const int wid  = tid >> 5;
    const int wm   = wid & 3;
    const int wn   = wid >> 2;
    const int tb   = blockIdx.x * MT;
    const int ob   = blockIdx.y * NT;

    const uint32_t sb   = smem_u32(dsmem);
    const uint32_t A_hi = sb;
    const uint32_t A_lo = sb + OFF_ALO;
    const uint32_t Bbas = sb + OFF_B;
    float* sg = reinterpret_cast<float*>(dsmem + OFF_G);

    const uint32_t laneA  = (uint32_t)(((lane & 7) + ((lane >> 3) & 1) * 8) * RS
                                       + ((lane >> 4) & 1) * 16);
    const uint32_t laneB4 = (uint32_t)(((lane & 7) + ((lane >> 4) & 1) * 8) * RS
                                       + ((lane >> 3) & 1) * 16);
    const int li = lane & 15;
    const uint32_t laneB2 = (uint32_t)((li & 7) * RS + (li >> 3) * 16);

    const int grp  = lane >> 2;
    const int rofs = wm * 32 + grp;      // row (mi=0, sub 0) within tile

    // stage gates [128 x 8] to smem
#pragma unroll
    for (int t = 0; t < 2; t++) {
        int i = tid + t * 512;
        sg[i] = g_gates[(size_t)(tb + (i >> 3)) * N_EXP + (i & 7)];
    }

    float outacc[2][5][4];
#pragma unroll
    for (int i = 0; i < 2; i++)
#pragma unroll
        for (int j = 0; j < 5; j++)
#pragma unroll
            for (int q = 0; q < 4; q++) outacc[i][j][q] = 0.f;

    for (int c = 0; c < NCHUNK; c++) {
        const int c0 = c * KC;
        __syncthreads();   // previous chunk's compute done (also covers sg on c=0)

        // ---- stage A via cp.async ----
        {
            int row = tid >> 2, c8 = tid & 3;
            size_t gi = (size_t)(tb + row) * D_IN + c0 + c8 * 8;
            uint32_t dof = (uint32_t)(row * RS + c8 * 16);
            cp_async16(A_hi + dof, g_xhi + gi);
            cp_async16(A_lo + dof, g_xlo + gi);
        }
        // ---- stage B via cp.async ----
#pragma unroll
        for (int t = 0; t < 20; t++) {
            int i = tid + t * 512;
            int e = i / 1280;
            int rem = i - e * 1280;
            int lohalf = rem >= 640;
            int rr = lohalf ? rem - 640 : rem;
            int r = rr >> 2, c8 = rr & 3;
            const __nv_bfloat16* src = lohalf ? g_wlo : g_whi;
            cp_async16(Bbas + (uint32_t)(e * (2 * B_BYTES) + lohalf * B_BYTES
                                         + r * RS + c8 * 16),
                       src + ((size_t)e * O_PAD + ob + r) * D_IN + c0 + c8 * 8);
        }
        cp_commit_wait0();
        __syncthreads();

#pragma unroll
        for (int ks = 0; ks < 2; ks++) {
            // A fragments resident for all experts & passes of this kstep
            uint32_t ah[2][4], al[2][4];
#pragma unroll
            for (int mi = 0; mi < 2; mi++) {
                uint32_t ao = laneA + (uint32_t)((wm * 32 + mi * 16) * RS + ks * 32);
                ldsm_x4(ah[mi], A_hi + ao);
                ldsm_x4(al[mi], A_lo + ao);
            }

#pragma unroll 1
            for (int e = 0; e < N_EXP; e++) {
                const uint32_t Bh = Bbas + (uint32_t)(e * (2 * B_BYTES));
                const uint32_t Bl = Bh + B_BYTES;
                const uint32_t bo4a = laneB4 + (uint32_t)((wn * 40) * RS + ks * 32);
                const uint32_t bo4b = laneB4 + (uint32_t)((wn * 40 + 16) * RS + ks * 32);
                const uint32_t bo2  = laneB2 + (uint32_t)((wn * 40 + 32) * RS + ks * 32);

                float dd[2][5][4];
#pragma unroll
                for (int i = 0; i < 2; i++)
#pragma unroll
                    for (int j = 0; j < 5; j++)
#pragma unroll
                        for (int q = 0; q < 4; q++) dd[i][j][q] = 0.f;

                uint32_t b4a[4], b4b[4], b2[2];
                // B_hi: used by pass0 (A_hi) and pass2 (A_lo)
                ldsm_x4(b4a, Bh + bo4a);
                ldsm_x4(b4b, Bh + bo4b);
                ldsm_x2(b2,  Bh + bo2);
#pragma unroll
                for (int mi = 0; mi < 2; mi++) {
                    mma_bf16(dd[mi][0], ah[mi], b4a);
                    mma_bf16(dd[mi][1], ah[mi], b4a + 2);
                    mma_bf16(dd[mi][2], ah[mi], b4b);
                    mma_bf16(dd[mi][3], ah[mi], b4b + 2);
                    mma_bf16(dd[mi][4], ah[mi], b2);
                    mma_bf16(dd[mi][0], al[mi], b4a);
                    mma_bf16(dd[mi][1], al[mi], b4a + 2);
                    mma_bf16(dd[mi][2], al[mi], b4b);
                    mma_bf16(dd[mi][3], al[mi], b4b + 2);
                    mma_bf16(dd[mi][4], al[mi], b2);
                }
                // B_lo: pass1 (A_hi), reuse same registers
                ldsm_x4(b4a, Bl + bo4a);
                ldsm_x4(b4b, Bl + bo4b);
                ldsm_x2(b2,  Bl + bo2);
#pragma unroll
                for (int mi = 0; mi < 2; mi++) {
                    mma_bf16(dd[mi][0], ah[mi], b4a);
                    mma_bf16(dd[mi][1], ah[mi], b4a + 2);
                    mma_bf16(dd[mi][2], ah[mi], b4b);
                    mma_bf16(dd[mi][3], ah[mi], b4b + 2);
                    mma_bf16(dd[mi][4], ah[mi], b2);
                }

                // ---- fold: outacc += g * dd (exact: fold is linear) ----
                float g0 = sg[(rofs)      * N_EXP + e];
                float g1 = sg[(rofs + 8)  * N_EXP + e];
                float g2 = sg[(rofs + 16) * N_EXP + e];
                float g3 = sg[(rofs + 24) * N_EXP + e];
#pragma unroll
                for (int nt = 0; nt < 5; nt++) {
                    outacc[0][nt][0] += g0 * dd[0][nt][0];
                    outacc[0][nt][1] += g0 * dd[0][nt][1];
                    outacc[0][nt][2] += g1 * dd[0][nt][2];
                    outacc[0][nt][3] += g1 * dd[0][nt][3];
                    outacc[1][nt][0] += g2 * dd[1][nt][0];
                    outacc[1][nt][1] += g2 * dd[1][nt][1];
                    outacc[1][nt][2] += g3 * dd[1][nt][2];
                    outacc[1][nt][3] += g3 * dd[1][nt][3];
                }
            }
        }
    }

    // ---- epilogue: out = outacc - gbw ----
#pragma unroll
    for (int mi = 0; mi < 2; mi++) {
        const int t0 = tb + rofs + mi * 16;
#pragma unroll
        for (int nt = 0; nt < 5; nt++) {
            const int o = ob + wn * 40 + nt * 8 + (lane & 3) * 2;
            if (o < O_OUT) {
                {
                    const float2 gb = *reinterpret_cast<const float2*>(
                        g_gbw + (size_t)t0 * O_OUT + o);
                    float2 w = make_float2(outacc[mi][nt][0] - gb.x,
                                           outacc[mi][nt][1] - gb.y);
                    *reinterpret_cast<float2*>(out + (size_t)t0 * O_OUT + o) = w;
                }
                {
                    const int t1 = t0 + 8;
                    const float2 gb = *reinterpret_cast<const float2*>(
                        g_gbw + (size_t)t1 * O_OUT + o);
                    float2 w = make_float2(outacc[mi][nt][2] - gb.x,
                                           outacc[mi][nt][3] - gb.y);
                    *reinterpret_cast<float2*>(out + (size_t)t1 * O_OUT + o) = w;
                }
            }
        }
    }
}

// ---------------------------------------------------------------------------
extern "C" void kernel_launch(void* const* d_in, const int* in_sizes, int n_in,
                              void* d_out, int out_size)
{
    const float* x           = (const float*)d_in[0];
    const float* w_gate      = (const float*)d_in[1];
    const float* expert_w    = (const float*)d_in[2];
    const float* expert_bias = (const float*)d_in[3];
    float* out = (float*)d_out;
    (void)in_sizes; (void)n_in; (void)out_size;

    cudaFuncSetAttribute(moe_hmma_kernel,
                         cudaFuncAttributeMaxDynamicSharedMemorySize, SMEM_MAIN);

    prologue_kernel<<<NG + NPX + NPW, 256>>>(x, w_gate, expert_w);
    bw_gbw_kernel<<<dim3(L_SEQ, O_OUT / OCH), 256>>>(expert_bias, expert_w);
    moe_hmma_kernel<<<dim3(T_TOK / MT, O_PAD / NT), 512, SMEM_MAIN>>>(out);
}